// round 9
// baseline (speedup 1.0000x reference)
#include <cuda_runtime.h>
#include <cuda_bf16.h>

#define W_IN 160
#define H_IN 160
#define HW   (H_IN * W_IN)
#define C_IN 256
#define POOLED 7
#define MAXT 5                     // max footprint side (3*sw <= 2.16 => <=5)
#define MAXSTRIDE 25

__device__ __forceinline__ void cp_async4(float* smem_dst, const float* gmem_src) {
    unsigned s = (unsigned)__cvta_generic_to_shared(smem_dst);
    asm volatile("cp.async.ca.shared.global [%0], [%1], 4;\n" :: "r"(s), "l"(gmem_src));
}

__global__ __launch_bounds__(C_IN, 6)
void dcnv2_pool_kernel(const float* __restrict__ inp,
                       const float* __restrict__ rois,
                       const float* __restrict__ offset,
                       float* __restrict__ out,
                       int N)
{
    __shared__ float tile[C_IN * MAXSTRIDE];     // 25.6 KB

    const int bin = blockIdx.x;
    const int n   = blockIdx.y;
    const int ph  = bin / POOLED;
    const int pw  = bin % POOLED;
    const int tid = threadIdx.x;
    const int lane = tid & 31;
    const int warp = tid >> 5;

    // ---- ROI geometry (uniform across block; per-thread registers) ----
    const float* roi = rois + n * 5;
    const int   b  = (int)__ldg(&roi[0]);
    const float rsw = rintf(__ldg(&roi[1])) * 0.0625f - 0.5f;
    const float rsh = rintf(__ldg(&roi[2])) * 0.0625f - 0.5f;
    const float rew = (rintf(__ldg(&roi[3])) + 1.0f) * 0.0625f - 0.5f;
    const float reh = (rintf(__ldg(&roi[4])) + 1.0f) * 0.0625f - 0.5f;
    const float rw  = fmaxf(rew - rsw, 0.1f);
    const float rh  = fmaxf(reh - rsh, 0.1f);
    const float bw  = rw * (1.0f / 7.0f);
    const float bh  = rh * (1.0f / 7.0f);
    const float sw  = bw * 0.25f;
    const float sh  = bh * 0.25f;

    const float tx = __ldg(&offset[((n * 2 + 0) * POOLED + ph) * POOLED + pw]) * 0.1f;
    const float ty = __ldg(&offset[((n * 2 + 1) * POOLED + ph) * POOLED + pw]) * 0.1f;

    const float wstart = pw * bw + rsw + tx * rw;
    const float hstart = ph * bh + rsh + ty * rh;

    // ---- exact clipped footprint (x,y monotone in sample index) ----
    const float xcA = fminf(fmaxf(wstart,             0.0f), (float)(W_IN - 1));
    const float xcB = fminf(fmaxf(wstart + 3.0f * sw, 0.0f), (float)(W_IN - 1));
    const float ycA = fminf(fmaxf(hstart,             0.0f), (float)(H_IN - 1));
    const float ycB = fminf(fmaxf(hstart + 3.0f * sh, 0.0f), (float)(H_IN - 1));
    const int xlo = (int)floorf(xcA);
    const int ylo = (int)floorf(ycA);
    const int w   = min((int)ceilf(xcB) - xlo + 1, MAXT);   // 1..5, fully in-image
    const int h   = min((int)ceilf(ycB) - ylo + 1, MAXT);
    const int area   = w * h;                               // <= 25
    const int stride = area | 1;                            // odd -> conflict-free

    // ---- stage footprint with cp.async (warp-local) ----
    {
        const int yy  = lane / w;
        const int xx  = lane - yy * w;
        const int off = (ylo + yy) * W_IN + (xlo + xx);     // in-image by construction
        const float* gp = inp + (size_t)b * (C_IN * HW) + (size_t)(warp * 32) * HW + off;
        float* sp = tile + (warp * 32) * stride + lane;
        if (lane < area) {
            #pragma unroll
            for (int i = 0; i < 32; i++) {
                cp_async4(sp, gp);
                gp += HW;
                sp += stride;
            }
        }
        asm volatile("cp.async.commit_group;\n" ::: "memory");
    }

    // ---- lane-parallel separable weights (overlaps cp.async flight) ----
    // Lanes 0..4: WX[lane]; lanes 5..9: WY[lane-5]. cntX at lane 0, cntY at lane 5.
    // WX[e] = sum_s okX * hat(xc_s - (xlo+e)); hat(d)=max(0,1-|d|) reproduces
    // floor/ceil bilinear splitting exactly (incl. d==0). cnt = cntX*cntY.
    float wval = 0.0f, cval = 0.0f;
    if (lane < 10) {
        const bool  isX    = lane < 5;
        const int   e      = isX ? lane : lane - 5;
        const float start  = isX ? wstart : hstart;
        const float step   = isX ? sw : sh;
        const float lim    = isX ? (float)W_IN : (float)H_IN;
        const float anchor = (float)((isX ? xlo : ylo) + e);
        #pragma unroll
        for (int s = 0; s < 4; s++) {
            const float v   = start + (float)s * step;
            const float okv = (v >= -0.5f && v <= lim - 0.5f) ? 1.0f : 0.0f;
            const float vc  = fminf(fmaxf(v, 0.0f), lim - 1.0f);
            cval += okv;
            wval += okv * fmaxf(1.0f - fabsf(vc - anchor), 0.0f);
        }
    }
    float WX[MAXT], WY[MAXT];
    #pragma unroll
    for (int e = 0; e < MAXT; e++) {
        WX[e] = __shfl_sync(0xffffffffu, wval, e);
        WY[e] = __shfl_sync(0xffffffffu, wval, 5 + e);
    }
    const float cnt = __shfl_sync(0xffffffffu, cval, 0)
                    * __shfl_sync(0xffffffffu, cval, 5);

    asm volatile("cp.async.wait_group 0;\n" ::: "memory");
    __syncwarp();                                // staging is warp-local

    // ---- thread = channel: separable dot over footprint ----
    const float* tch = tile + tid * stride;
    float acc = 0.0f;
    #pragma unroll
    for (int yy = 0; yy < MAXT; yy++) {
        if (yy < h) {
            float r = 0.0f;
            #pragma unroll
            for (int xx = 0; xx < MAXT; xx++) {
                if (xx < w) r += WX[xx] * tch[yy * w + xx];
            }
            acc += WY[yy] * r;
        }
    }

    out[(((size_t)n * C_IN + tid) * POOLED + ph) * POOLED + pw] =
        acc / fmaxf(cnt, 1.0f);
}

extern "C" void kernel_launch(void* const* d_in, const int* in_sizes, int n_in,
                              void* d_out, int out_size)
{
    const float* inp    = (const float*)d_in[0];   // (2, 256, 160, 160) f32
    const float* rois   = (const float*)d_in[1];   // (N, 5) f32
    const float* offset = (const float*)d_in[2];   // (N, 2, 7, 7) f32
    float* out = (float*)d_out;                    // (N, 256, 7, 7) f32

    const int N = in_sizes[1] / 5;

    dim3 grid(POOLED * POOLED, N);                 // 49 x N
    dim3 block(C_IN);
    dcnv2_pool_kernel<<<grid, block>>>(inp, rois, offset, out, N);
}